// round 14
// baseline (speedup 1.0000x reference)
#include <cuda_runtime.h>
#include <cuda_bf16.h>
#include <cstdint>

#define B 512
#define COND 64
#define NN 256
#define NE 32640
#define OUT2 65280
#define D1 256
#define D2 512
#define D3 1024
#define EPAD 32768
#define FIXCAP (1 << 20)
#define THRESH 2e-4f

// ---------------- scratch ----------------
__device__ __nv_bfloat16 g_h3hi[B * D3];
__device__ float g_h3f[B * D3];
__device__ __nv_bfloat16 g_wd[2 * D3 * NE];    // 134 MB: bf16 weight diffs, K-MAJOR [ex][k][edge]
__device__ int g_perm[B];
__device__ int g_cnt[2];
__device__ unsigned char g_edges[B * EPAD];
__device__ int g_fix_cnt;
__device__ uint32_t g_fix[FIXCAP];

// ---------------- helpers ----------------
__device__ __forceinline__ uint32_t smem_u32(const void* p) {
    uint32_t a;
    asm("{ .reg .u64 t; cvta.to.shared.u64 t, %1; cvt.u32.u64 %0, t; }" : "=r"(a) : "l"(p));
    return a;
}
__device__ __forceinline__ void ldm_x4(uint32_t& r0, uint32_t& r1, uint32_t& r2, uint32_t& r3,
                                       uint32_t addr) {
    asm volatile("ldmatrix.sync.aligned.m8n8.x4.shared.b16 {%0,%1,%2,%3}, [%4];"
                 : "=r"(r0), "=r"(r1), "=r"(r2), "=r"(r3) : "r"(addr));
}
__device__ __forceinline__ void ldm_x4_trans(uint32_t& r0, uint32_t& r1, uint32_t& r2, uint32_t& r3,
                                             uint32_t addr) {
    asm volatile("ldmatrix.sync.aligned.m8n8.x4.trans.shared.b16 {%0,%1,%2,%3}, [%4];"
                 : "=r"(r0), "=r"(r1), "=r"(r2), "=r"(r3) : "r"(addr));
}
__device__ __forceinline__ void mma_bf16(float* c, uint32_t a0, uint32_t a1, uint32_t a2,
                                         uint32_t a3, uint32_t b0, uint32_t b1) {
    asm volatile(
        "mma.sync.aligned.m16n8k16.row.col.f32.bf16.bf16.f32 "
        "{%0,%1,%2,%3}, {%4,%5,%6,%7}, {%8,%9}, {%0,%1,%2,%3};"
        : "+f"(c[0]), "+f"(c[1]), "+f"(c[2]), "+f"(c[3])
        : "r"(a0), "r"(a1), "r"(a2), "r"(a3), "r"(b0), "r"(b1));
}
__device__ __forceinline__ void cp16(uint32_t dst, const void* src) {
    asm volatile("cp.async.cg.shared.global [%0], [%1], 16;" :: "r"(dst), "l"(src));
}
#define CP_COMMIT() asm volatile("cp.async.commit_group;" ::: "memory")
#define CP_WAIT(n)  asm volatile("cp.async.wait_group %0;" :: "n"(n) : "memory")

// ---------------- kernel A: partition by expert ----------------
__global__ void k_group(const float* __restrict__ x) {
    __shared__ int cnt[2];
    int t = threadIdx.x;
    if (t < 2) cnt[t] = 0;
    __syncthreads();
    int big = (x[t * COND] > 0.0f) ? 1 : 0;
    int p = atomicAdd(&cnt[big ? 0 : 1], 1);
    g_perm[big ? p : (B - 1 - p)] = t;
    __syncthreads();
    if (t == 0) { g_cnt[0] = cnt[0]; g_cnt[1] = cnt[1]; g_fix_cnt = 0; }
}

// ---------------- kernel W: W3 diffs -> bf16, K-MAJOR, edge-range [8*c0, 8*c1) ----------------
__global__ __launch_bounds__(256) void k_wdiff(
    const float* __restrict__ bw3, const float* __restrict__ sw3,
    int c0, int c1)
{
    int kr = blockIdx.x;
    int ex = blockIdx.y;
    const float* src = (ex ? sw3 : bw3) + (size_t)kr * OUT2;
    __nv_bfloat16* dst = g_wd + (size_t)ex * D3 * NE + (size_t)kr * NE;
    int t = threadIdx.x;
#pragma unroll 2
    for (int i = c0 + t; i < c1; i += 256) {
        const float4* s4 = (const float4*)(src + i * 16);
        float4 w0 = s4[0], w1 = s4[1], w2 = s4[2], w3v = s4[3];
        union { __nv_bfloat162 h[4]; uint4 v; } pk;
        pk.h[0] = __floats2bfloat162_rn(w0.x - w0.y, w0.z - w0.w);
        pk.h[1] = __floats2bfloat162_rn(w1.x - w1.y, w1.z - w1.w);
        pk.h[2] = __floats2bfloat162_rn(w2.x - w2.y, w2.z - w2.w);
        pk.h[3] = __floats2bfloat162_rn(w3v.x - w3v.y, w3v.z - w3v.w);
        *(uint4*)(dst + i * 8) = pk.v;
    }
}

// ---------------- kernel B: trunk 64->256->512->1024, outputs bf16 + fp32 ----------------
__global__ __launch_bounds__(256) void k_hidden(
    const float* __restrict__ x,
    const float* __restrict__ bw0, const float* __restrict__ bb0,
    const float* __restrict__ bw1, const float* __restrict__ bb1,
    const float* __restrict__ bw2, const float* __restrict__ bb2,
    const float* __restrict__ sw0, const float* __restrict__ sb0,
    const float* __restrict__ sw1, const float* __restrict__ sb1,
    const float* __restrict__ sw2, const float* __restrict__ sb2)
{
    __shared__ float xs[8][COND];
    __shared__ float h1s[8][D1];
    __shared__ float h2s[8][D2];
    __shared__ int bi[8];

    int t = threadIdx.x;
    int g = blockIdx.x;
    int qh = blockIdx.y;
    if (t < 8) bi[t] = g_perm[g * 8 + t];
    __syncthreads();
    int nbig = g_cnt[0];

    for (int i = t; i < 8 * COND; i += 256) {
        int s = i >> 6, k = i & 63;
        xs[s][k] = x[bi[s] * COND + k];
    }
    __syncthreads();

    for (int ex = 0; ex < 2; ex++) {
        bool own[8]; bool anyown = false;
#pragma unroll
        for (int s = 0; s < 8; s++) {
            own[s] = (((g * 8 + s) < nbig ? 0 : 1) == ex);
            anyown |= own[s];
        }
        if (!anyown) continue;

        const float* W0 = ex ? sw0 : bw0; const float* B0 = ex ? sb0 : bb0;
        const float* W1 = ex ? sw1 : bw1; const float* B1 = ex ? sb1 : bb1;
        const float* W2 = ex ? sw2 : bw2; const float* B2 = ex ? sb2 : bb2;

        { // L1
            float acc[8];
#pragma unroll
            for (int s = 0; s < 8; s++) acc[s] = 0.f;
#pragma unroll 4
            for (int k = 0; k < COND; k++) {
                float w = W0[k * D1 + t];
#pragma unroll
                for (int s = 0; s < 8; s++) acc[s] = fmaf(xs[s][k], w, acc[s]);
            }
            float bb = B0[t];
#pragma unroll
            for (int s = 0; s < 8; s++) h1s[s][t] = fmaxf(acc[s] + bb, 0.f);
        }
        __syncthreads();

        { // L2
            float a0[8], a1[8];
#pragma unroll
            for (int s = 0; s < 8; s++) { a0[s] = 0.f; a1[s] = 0.f; }
#pragma unroll 4
            for (int k = 0; k < D1; k++) {
                float w0 = W1[k * D2 + t];
                float w1 = W1[k * D2 + t + 256];
#pragma unroll
                for (int s = 0; s < 8; s++) {
                    float h = h1s[s][k];
                    a0[s] = fmaf(h, w0, a0[s]);
                    a1[s] = fmaf(h, w1, a1[s]);
                }
            }
            float b0v = B1[t], b1v = B1[t + 256];
#pragma unroll
            for (int s = 0; s < 8; s++) {
                h2s[s][t]       = fmaxf(a0[s] + b0v, 0.f);
                h2s[s][t + 256] = fmaxf(a1[s] + b1v, 0.f);
            }
        }
        __syncthreads();

        { // L3 (this block's half)
            float acc[2][8];
#pragma unroll
            for (int q = 0; q < 2; q++)
#pragma unroll
                for (int s = 0; s < 8; s++) acc[q][s] = 0.f;
            int c0 = t + (qh * 2 + 0) * 256;
            int c1 = t + (qh * 2 + 1) * 256;
#pragma unroll 2
            for (int k = 0; k < D2; k++) {
                float w0 = W2[k * D3 + c0];
                float w1 = W2[k * D3 + c1];
#pragma unroll
                for (int s = 0; s < 8; s++) {
                    float h = h2s[s][k];
                    acc[0][s] = fmaf(h, w0, acc[0][s]);
                    acc[1][s] = fmaf(h, w1, acc[1][s]);
                }
            }
#pragma unroll
            for (int q = 0; q < 2; q++) {
                int neuron = t + (qh * 2 + q) * 256;
                float bq = B2[neuron];
#pragma unroll
                for (int s = 0; s < 8; s++) {
                    if (own[s]) {
                        float v = fmaxf(acc[q][s] + bq, 0.f);
                        g_h3hi[bi[s] * D3 + neuron] = __float2bfloat16_rn(v);
                        g_h3f[bi[s] * D3 + neuron] = v;
                    }
                }
            }
        }
        __syncthreads();
    }
}

// ---------------- kernel C: bf16 GEMM, k-major B via ldmatrix.trans ----------------
// grid (8, ny): x = row-tile (expert = x>>2, tile = x&3), y + yoff = n-tile.
#define TSTRIDE 80
#define BSTRIDE 272
#define A_SZ 10240
#define B_SZ 8704
#define BOFF 20480
#define BYTESTRIDE 136

__global__ __launch_bounds__(256) void k_gemm(
    const float* __restrict__ gumbel,
    const float* __restrict__ bw3, const float* __restrict__ bb3,
    const float* __restrict__ sw3, const float* __restrict__ sb3,
    int yoff)
{
    __shared__ __align__(16) char sbuf[BOFF + 2 * B_SZ];
    __shared__ int batch_s[128];
    __shared__ float bdiff_s[128];

    int t = threadIdx.x;
    int wid = t >> 5;
    int lane = t & 31;
    int expert = blockIdx.x >> 2;
    int tile = blockIdx.x & 3;
    int nbig = g_cnt[0];
    int cnt = expert ? (B - nbig) : nbig;
    int base = expert ? nbig : 0;
    int rbase = tile * 128;
    int rows = cnt - rbase;
    if (rows <= 0) return;
    if (rows > 128) rows = 128;
    int n0 = (blockIdx.y + yoff) * 128;

    const float* B3 = expert ? sb3 : bb3;

    if (t < 128) {
        int r = t < rows ? t : (rows - 1);
        batch_s[t] = g_perm[base + rbase + r];
        float2 bp = *(const float2*)(B3 + 2 * (n0 + t));
        bdiff_s[t] = bp.x - bp.y;
    }
    __syncthreads();

    float acc[4][4][4];
#pragma unroll
    for (int i = 0; i < 4; i++)
#pragma unroll
        for (int jj = 0; jj < 4; jj++)
#pragma unroll
            for (int r = 0; r < 4; r++) acc[i][jj][r] = 0.f;

    const uint32_t sb0 = smem_u32(sbuf);
    const int mbase = (wid >> 2) * 64;
    const int nbase = (wid & 3) * 32;
    const int lrow = lane & 15;
    const int lsel = lane >> 4;

    const int cr = t >> 1;
    const int ch = t & 1;
    const __nv_bfloat16* asrc = g_h3hi + (size_t)batch_s[cr] * D3 + ch * 16;
    const uint32_t adst = sb0 + cr * TSTRIDE + ch * 32;
    const int br = t >> 3;
    const int bs = t & 7;
    const __nv_bfloat16* bsrc = g_wd + (size_t)expert * D3 * NE + (size_t)br * NE + n0 + bs * 16;
    const uint32_t bdst = sb0 + BOFF + br * BSTRIDE + bs * 32;

#define ISSUE_CHUNK(stg, jj)                                             \
    do {                                                                 \
        uint32_t _ad = adst + (stg) * A_SZ;                              \
        uint32_t _bd = bdst + (stg) * B_SZ;                              \
        const __nv_bfloat16* _as = asrc + (jj) * 32;                     \
        const __nv_bfloat16* _bs = bsrc + (size_t)(jj) * 32 * NE;        \
        cp16(_ad, _as); cp16(_ad + 16, _as + 8);                         \
        cp16(_bd, _bs); cp16(_bd + 16, _bs + 8);                         \
        CP_COMMIT();                                                     \
    } while (0)

    ISSUE_CHUNK(0, 0);

#pragma unroll 1
    for (int j = 0; j < 32; j++) {
        int stg = j & 1;
        if (j < 31) {
            ISSUE_CHUNK(stg ^ 1, j + 1);
            CP_WAIT(1);
        } else {
            CP_WAIT(0);
        }
        __syncthreads();

        uint32_t abase = sb0 + stg * A_SZ;
        uint32_t bbase = sb0 + BOFF + stg * B_SZ;
#pragma unroll
        for (int ks = 0; ks < 2; ks++) {
            uint32_t bh[2][4];
#pragma unroll
            for (int bg = 0; bg < 2; bg++) {
                uint32_t addr = bbase
                    + (uint32_t)((ks * 16 + (lane & 7) + ((lane >> 4) << 3)) * BSTRIDE)
                    + (uint32_t)((nbase + bg * 16 + ((lane >> 3) & 1) * 8) * 2);
                ldm_x4_trans(bh[bg][0], bh[bg][1], bh[bg][2], bh[bg][3], addr);
            }
            uint32_t koff = (uint32_t)((ks * 16 + lsel * 8) * 2);
            uint32_t af[4][4];
#pragma unroll
            for (int mf = 0; mf < 4; mf++) {
                uint32_t rowoff = (uint32_t)((mbase + mf * 16 + lrow) * TSTRIDE) + koff;
                ldm_x4(af[mf][0], af[mf][1], af[mf][2], af[mf][3], abase + rowoff);
            }
#pragma unroll
            for (int mf = 0; mf < 4; mf++)
#pragma unroll
                for (int nf = 0; nf < 4; nf++) {
                    int bg = nf >> 1, h = nf & 1;
                    mma_bf16(acc[mf][nf], af[mf][0], af[mf][1], af[mf][2], af[mf][3],
                             bh[bg][h], bh[bg][2 + h]);
                }
        }
        __syncthreads();
    }

    // ---- epilogue ----
    int g = lane >> 2, tid4 = lane & 3;
#pragma unroll
    for (int mf = 0; mf < 4; mf++) {
#pragma unroll
        for (int h = 0; h < 2; h++) {
            int mrow = mbase + mf * 16 + g + h * 8;
            bool valid = (mrow < rows);
            int bat = batch_s[mrow];
            const float2* gpr = (const float2*)(gumbel + (size_t)bat * OUT2 + 2 * n0);
#pragma unroll
            for (int nf = 0; nf < 4; nf++) {
                int ncol = nbase + nf * 8 + 2 * tid4;
                float2 gA = gpr[ncol];
                float2 gB = gpr[ncol + 1];
                float m0 = acc[mf][nf][h * 2 + 0] + bdiff_s[ncol]     + (gA.x - gA.y);
                float m1 = acc[mf][nf][h * 2 + 1] + bdiff_s[ncol + 1] + (gB.x - gB.y);
                unsigned short v = (unsigned short)((m0 >= 0.f ? 1 : 0) | ((m1 >= 0.f ? 1 : 0) << 8));
                *(unsigned short*)(sbuf + mrow * BYTESTRIDE + ncol) = v;
                if (valid) {
                    if (fabsf(m0) < THRESH) {
                        int ix = atomicAdd(&g_fix_cnt, 1);
                        if (ix < FIXCAP)
                            g_fix[ix] = ((uint32_t)expert << 24) | ((uint32_t)bat << 15)
                                      | (uint32_t)(n0 + ncol);
                    }
                    if (fabsf(m1) < THRESH) {
                        int ix = atomicAdd(&g_fix_cnt, 1);
                        if (ix < FIXCAP)
                            g_fix[ix] = ((uint32_t)expert << 24) | ((uint32_t)bat << 15)
                                      | (uint32_t)(n0 + ncol + 1);
                    }
                }
            }
        }
    }
    __syncthreads();

#pragma unroll
    for (int pass = 0; pass < 8; pass++) {
        int idx = pass * 256 + t;
        int r = idx >> 4, seg = idx & 15;
        if (r < rows) {
            uint2 v = *(const uint2*)(sbuf + r * BYTESTRIDE + seg * 8);
            *(uint2*)(g_edges + (size_t)batch_s[r] * EPAD + n0 + seg * 8) = v;
        }
    }
}

// ---------------- kernel C2: exact fp32 fixup for near-zero margins ----------------
__global__ __launch_bounds__(256) void k_fix(
    const float* __restrict__ gumbel,
    const float* __restrict__ bw3, const float* __restrict__ bb3,
    const float* __restrict__ sw3, const float* __restrict__ sb3)
{
    int n = g_fix_cnt;
    if (n > FIXCAP) n = FIXCAP;
    int nw = gridDim.x * 8;
    int w = blockIdx.x * 8 + (threadIdx.x >> 5);
    int lane = threadIdx.x & 31;
    for (int it = w; it < n; it += nw) {
        uint32_t v = g_fix[it];
        int ex = v >> 24;
        int bat = (v >> 15) & 511;
        int e = v & 32767;
        const float* W3 = ex ? sw3 : bw3;
        const float* B3 = ex ? sb3 : bb3;
        const float* h = g_h3f + (size_t)bat * D3;
        const float* wp = W3 + 2 * e;
        float a0 = 0.f, a1 = 0.f, a2 = 0.f, a3 = 0.f;
#pragma unroll 8
        for (int i = 0; i < 32; i++) {
            int k = lane + i * 32;
            float2 ww = *(const float2*)(wp + (size_t)k * OUT2);
            float p = h[k] * (ww.x - ww.y);
            if ((i & 3) == 0) a0 += p; else if ((i & 3) == 1) a1 += p;
            else if ((i & 3) == 2) a2 += p; else a3 += p;
        }
        float s = (a0 + a1) + (a2 + a3);
#pragma unroll
        for (int o = 16; o; o >>= 1) s += __shfl_xor_sync(0xFFFFFFFFu, s, o);
        if (lane == 0) {
            float2 g2 = *(const float2*)(gumbel + (size_t)bat * OUT2 + 2 * e);
            float m = s + (B3[2 * e] - B3[2 * e + 1]) + (g2.x - g2.y);
            g_edges[(size_t)bat * EPAD + e] = (m >= 0.f) ? 1 : 0;
        }
    }
}

// ---------------- kernel D: expand bits -> symmetric 256x256 fp32 ----------------
__global__ __launch_bounds__(256) void k_expand(float* __restrict__ out) {
    const int pi_ = blockIdx.y;
    int I0, J0;
    {
        const int pI[10] = {0,0,0,0,1,1,1,2,2,3};
        const int pJ[10] = {0,1,2,3,1,2,3,2,3,3};
        I0 = pI[pi_] * 64; J0 = pJ[pi_] * 64;
    }
    int b = blockIdx.x;
    __shared__ unsigned char s[64][68];
    const unsigned char* eb = g_edges + (size_t)b * EPAD;
    float* ob = out + (size_t)b * (NN * NN);
    int t = threadIdx.x;
    bool diag = (I0 == J0);

    int col = t & 63;
    int rg = t >> 6;
#pragma unroll 4
    for (int c = 0; c < 16; c++) {
        int il = rg * 16 + c;
        int i = I0 + il;
        int j = J0 + col;
        unsigned char v = 0;
        if (j > i) v = eb[(size_t)i * (511 - i) / 2 + (j - i - 1)];
        s[il][col] = v;
    }
    __syncthreads();

    int ilq = t >> 4;
    int jl = (t & 15) * 4;
#pragma unroll
    for (int p = 0; p < 4; p++) {
        int il = p * 16 + ilq;
        float4 v;
        if (diag) {
            int i = I0 + il;
            float vv[4];
#pragma unroll
            for (int c = 0; c < 4; c++) {
                int jj = J0 + jl + c;
                unsigned char u = (jj > i) ? s[il][jl + c] : ((jj < i) ? s[jl + c][il] : 0);
                vv[c] = (float)u;
            }
            v = make_float4(vv[0], vv[1], vv[2], vv[3]);
        } else {
            v = make_float4((float)s[il][jl], (float)s[il][jl + 1],
                            (float)s[il][jl + 2], (float)s[il][jl + 3]);
        }
        *(float4*)&ob[(I0 + il) * NN + J0 + jl] = v;
        if (!diag) {
            float4 w = make_float4((float)s[jl][il], (float)s[jl + 1][il],
                                   (float)s[jl + 2][il], (float)s[jl + 3][il]);
            *(float4*)&ob[(J0 + il) * NN + I0 + jl] = w;
        }
    }
}

// ---------------- launch ----------------
extern "C" void kernel_launch(void* const* d_in, const int* in_sizes, int n_in,
                              void* d_out, int out_size) {
    const float* x      = (const float*)d_in[0];
    const float* gumbel = (const float*)d_in[1];

    const float *bw[4], *bb[4], *sw[4], *sb[4];
    if (in_sizes[4] == 16384) {
        for (int l = 0; l < 4; l++) {
            bw[l] = (const float*)d_in[2 + 4 * l];
            bb[l] = (const float*)d_in[3 + 4 * l];
            sw[l] = (const float*)d_in[4 + 4 * l];
            sb[l] = (const float*)d_in[5 + 4 * l];
        }
    } else {
        for (int l = 0; l < 4; l++) {
            bw[l] = (const float*)d_in[2 + 2 * l];
            bb[l] = (const float*)d_in[3 + 2 * l];
            sw[l] = (const float*)d_in[10 + 2 * l];
            sb[l] = (const float*)d_in[11 + 2 * l];
        }
    }
    float* out = (float*)d_out;

    // one-time side stream + events (created on the uncaptured correctness call)
    static bool s_init = false;
    static cudaStream_t s_side = 0;
    static cudaEvent_t ev_fork = 0, ev_w0 = 0, ev_w1 = 0;
    if (!s_init) {
        s_init = true;
        if (cudaStreamCreateWithFlags(&s_side, cudaStreamNonBlocking) != cudaSuccess) {
            s_side = 0;
        } else if (cudaEventCreateWithFlags(&ev_fork, cudaEventDisableTiming) != cudaSuccess ||
                   cudaEventCreateWithFlags(&ev_w0, cudaEventDisableTiming) != cudaSuccess ||
                   cudaEventCreateWithFlags(&ev_w1, cudaEventDisableTiming) != cudaSuccess) {
            s_side = 0;
        }
    }

    if (s_side) {
        // fork side stream off the (captured) default stream
        cudaEventRecord(ev_fork, 0);
        cudaStreamWaitEvent(s_side, ev_fork, 0);
        // side stream: wdiff in two edge halves
        k_wdiff<<<dim3(1024, 2), 256, 0, s_side>>>(bw[3], sw[3], 0, 2048);
        cudaEventRecord(ev_w0, s_side);
        k_wdiff<<<dim3(1024, 2), 256, 0, s_side>>>(bw[3], sw[3], 2048, 4080);
        cudaEventRecord(ev_w1, s_side);
        // main stream: trunk, then gemm halves gated by wdiff halves
        k_group<<<1, B>>>(x);
        k_hidden<<<dim3(64, 2), 256>>>(x,
            bw[0], bb[0], bw[1], bb[1], bw[2], bb[2],
            sw[0], sb[0], sw[1], sb[1], sw[2], sb[2]);
        cudaStreamWaitEvent(0, ev_w0, 0);
        k_gemm<<<dim3(8, 128), 256>>>(gumbel, bw[3], bb[3], sw[3], sb[3], 0);
        cudaStreamWaitEvent(0, ev_w1, 0);
        k_gemm<<<dim3(8, 127), 256>>>(gumbel, bw[3], bb[3], sw[3], sb[3], 128);
    } else {
        // serial fallback
        k_group<<<1, B>>>(x);
        k_wdiff<<<dim3(1024, 2), 256>>>(bw[3], sw[3], 0, 4080);
        k_hidden<<<dim3(64, 2), 256>>>(x,
            bw[0], bb[0], bw[1], bb[1], bw[2], bb[2],
            sw[0], sb[0], sw[1], sb[1], sw[2], sb[2]);
        k_gemm<<<dim3(8, 255), 256>>>(gumbel, bw[3], bb[3], sw[3], sb[3], 0);
    }
    k_fix<<<296, 256>>>(gumbel, bw[3], bb[3], sw[3], sb[3]);
    k_expand<<<dim3(B, 10), 256>>>(out);
}

// round 15
// speedup vs baseline: 1.0978x; 1.0978x over previous
#include <cuda_runtime.h>
#include <cuda_bf16.h>
#include <cstdint>

#define B 512
#define COND 64
#define NN 256
#define NE 32640
#define OUT2 65280
#define D1 256
#define D2 512
#define D3 1024
#define EPAD 32768
#define FIXCAP (1 << 20)
#define THRESH 2e-4f

// ---------------- scratch ----------------
__device__ __nv_bfloat16 g_h3hi[B * D3];
__device__ float g_h3f[B * D3];
__device__ __nv_bfloat16 g_wd[2 * D3 * NE];    // 134 MB: bf16 weight diffs, K-MAJOR [ex][k][edge]
__device__ int g_perm[B];
__device__ int g_cnt[2];
__device__ unsigned char g_edges[B * EPAD];
__device__ int g_fix_cnt;
__device__ uint32_t g_fix[FIXCAP];

// ---------------- helpers ----------------
__device__ __forceinline__ uint32_t smem_u32(const void* p) {
    uint32_t a;
    asm("{ .reg .u64 t; cvta.to.shared.u64 t, %1; cvt.u32.u64 %0, t; }" : "=r"(a) : "l"(p));
    return a;
}
__device__ __forceinline__ void ldm_x4(uint32_t& r0, uint32_t& r1, uint32_t& r2, uint32_t& r3,
                                       uint32_t addr) {
    asm volatile("ldmatrix.sync.aligned.m8n8.x4.shared.b16 {%0,%1,%2,%3}, [%4];"
                 : "=r"(r0), "=r"(r1), "=r"(r2), "=r"(r3) : "r"(addr));
}
__device__ __forceinline__ void ldm_x4_trans(uint32_t& r0, uint32_t& r1, uint32_t& r2, uint32_t& r3,
                                             uint32_t addr) {
    asm volatile("ldmatrix.sync.aligned.m8n8.x4.trans.shared.b16 {%0,%1,%2,%3}, [%4];"
                 : "=r"(r0), "=r"(r1), "=r"(r2), "=r"(r3) : "r"(addr));
}
__device__ __forceinline__ void mma_bf16(float* c, uint32_t a0, uint32_t a1, uint32_t a2,
                                         uint32_t a3, uint32_t b0, uint32_t b1) {
    asm volatile(
        "mma.sync.aligned.m16n8k16.row.col.f32.bf16.bf16.f32 "
        "{%0,%1,%2,%3}, {%4,%5,%6,%7}, {%8,%9}, {%0,%1,%2,%3};"
        : "+f"(c[0]), "+f"(c[1]), "+f"(c[2]), "+f"(c[3])
        : "r"(a0), "r"(a1), "r"(a2), "r"(a3), "r"(b0), "r"(b1));
}
__device__ __forceinline__ void cp16(uint32_t dst, const void* src) {
    asm volatile("cp.async.cg.shared.global [%0], [%1], 16;" :: "r"(dst), "l"(src));
}
#define CP_COMMIT() asm volatile("cp.async.commit_group;" ::: "memory")
#define CP_WAIT(n)  asm volatile("cp.async.wait_group %0;" :: "n"(n) : "memory")

// ---------------- kernel A: partition by expert ----------------
__global__ void k_group(const float* __restrict__ x) {
    __shared__ int cnt[2];
    int t = threadIdx.x;
    if (t < 2) cnt[t] = 0;
    __syncthreads();
    int big = (x[t * COND] > 0.0f) ? 1 : 0;
    int p = atomicAdd(&cnt[big ? 0 : 1], 1);
    g_perm[big ? p : (B - 1 - p)] = t;
    __syncthreads();
    if (t == 0) { g_cnt[0] = cnt[0]; g_cnt[1] = cnt[1]; g_fix_cnt = 0; }
}

// ---------------- kernel W: W3 diffs -> bf16, K-MAJOR (streaming) ----------------
__global__ __launch_bounds__(256) void k_wdiff(
    const float* __restrict__ bw3, const float* __restrict__ sw3)
{
    int kr = blockIdx.x;
    int ex = blockIdx.y;
    const float* src = (ex ? sw3 : bw3) + (size_t)kr * OUT2;
    __nv_bfloat16* dst = g_wd + (size_t)ex * D3 * NE + (size_t)kr * NE;
    int t = threadIdx.x;
#pragma unroll 2
    for (int i = t; i < 4080; i += 256) {
        const float4* s4 = (const float4*)(src + i * 16);
        float4 w0 = s4[0], w1 = s4[1], w2 = s4[2], w3v = s4[3];
        union { __nv_bfloat162 h[4]; uint4 v; } pk;
        pk.h[0] = __floats2bfloat162_rn(w0.x - w0.y, w0.z - w0.w);
        pk.h[1] = __floats2bfloat162_rn(w1.x - w1.y, w1.z - w1.w);
        pk.h[2] = __floats2bfloat162_rn(w2.x - w2.y, w2.z - w2.w);
        pk.h[3] = __floats2bfloat162_rn(w3v.x - w3v.y, w3v.z - w3v.w);
        *(uint4*)(dst + i * 8) = pk.v;
    }
}

// ---------------- kernel B: trunk, 4 batches/block, grid (128, 2) ----------------
__global__ __launch_bounds__(256) void k_hidden(
    const float* __restrict__ x,
    const float* __restrict__ bw0, const float* __restrict__ bb0,
    const float* __restrict__ bw1, const float* __restrict__ bb1,
    const float* __restrict__ bw2, const float* __restrict__ bb2,
    const float* __restrict__ sw0, const float* __restrict__ sb0,
    const float* __restrict__ sw1, const float* __restrict__ sb1,
    const float* __restrict__ sw2, const float* __restrict__ sb2)
{
    __shared__ float xs[4][COND];
    __shared__ float h1s[4][D1];
    __shared__ float h2s[4][D2];
    __shared__ int bi[4];

    int t = threadIdx.x;
    int g = blockIdx.x;       // 0..127: 4-batch group
    int qh = blockIdx.y;      // 0/1: L3 half
    if (t < 4) bi[t] = g_perm[g * 4 + t];
    __syncthreads();
    int nbig = g_cnt[0];

    for (int i = t; i < 4 * COND; i += 256) {
        int s = i >> 6, k = i & 63;
        xs[s][k] = x[bi[s] * COND + k];
    }
    __syncthreads();

    for (int ex = 0; ex < 2; ex++) {
        bool own[4]; bool anyown = false;
#pragma unroll
        for (int s = 0; s < 4; s++) {
            own[s] = (((g * 4 + s) < nbig ? 0 : 1) == ex);
            anyown |= own[s];
        }
        if (!anyown) continue;

        const float* W0 = ex ? sw0 : bw0; const float* B0 = ex ? sb0 : bb0;
        const float* W1 = ex ? sw1 : bw1; const float* B1 = ex ? sb1 : bb1;
        const float* W2 = ex ? sw2 : bw2; const float* B2 = ex ? sb2 : bb2;

        { // L1: 64 -> 256
            float acc[4];
#pragma unroll
            for (int s = 0; s < 4; s++) acc[s] = 0.f;
#pragma unroll 8
            for (int k = 0; k < COND; k++) {
                float w = W0[k * D1 + t];
#pragma unroll
                for (int s = 0; s < 4; s++) acc[s] = fmaf(xs[s][k], w, acc[s]);
            }
            float bb = B0[t];
#pragma unroll
            for (int s = 0; s < 4; s++) h1s[s][t] = fmaxf(acc[s] + bb, 0.f);
        }
        __syncthreads();

        { // L2: 256 -> 512
            float a0[4], a1[4];
#pragma unroll
            for (int s = 0; s < 4; s++) { a0[s] = 0.f; a1[s] = 0.f; }
#pragma unroll 8
            for (int k = 0; k < D1; k++) {
                float w0 = W1[k * D2 + t];
                float w1 = W1[k * D2 + t + 256];
#pragma unroll
                for (int s = 0; s < 4; s++) {
                    float h = h1s[s][k];
                    a0[s] = fmaf(h, w0, a0[s]);
                    a1[s] = fmaf(h, w1, a1[s]);
                }
            }
            float b0v = B1[t], b1v = B1[t + 256];
#pragma unroll
            for (int s = 0; s < 4; s++) {
                h2s[s][t]       = fmaxf(a0[s] + b0v, 0.f);
                h2s[s][t + 256] = fmaxf(a1[s] + b1v, 0.f);
            }
        }
        __syncthreads();

        { // L3: 512 -> 512 (this block's half)
            float acc[2][4];
#pragma unroll
            for (int q = 0; q < 2; q++)
#pragma unroll
                for (int s = 0; s < 4; s++) acc[q][s] = 0.f;
            int c0 = t + (qh * 2 + 0) * 256;
            int c1 = t + (qh * 2 + 1) * 256;
#pragma unroll 4
            for (int k = 0; k < D2; k++) {
                float w0 = W2[k * D3 + c0];
                float w1 = W2[k * D3 + c1];
#pragma unroll
                for (int s = 0; s < 4; s++) {
                    float h = h2s[s][k];
                    acc[0][s] = fmaf(h, w0, acc[0][s]);
                    acc[1][s] = fmaf(h, w1, acc[1][s]);
                }
            }
#pragma unroll
            for (int q = 0; q < 2; q++) {
                int neuron = t + (qh * 2 + q) * 256;
                float bq = B2[neuron];
#pragma unroll
                for (int s = 0; s < 4; s++) {
                    if (own[s]) {
                        float v = fmaxf(acc[q][s] + bq, 0.f);
                        g_h3hi[bi[s] * D3 + neuron] = __float2bfloat16_rn(v);
                        g_h3f[bi[s] * D3 + neuron] = v;
                    }
                }
            }
        }
        __syncthreads();
    }
}

// ---------------- kernel C: bf16 GEMM, k-major B via ldmatrix.trans ----------------
#define TSTRIDE 80
#define BSTRIDE 272
#define A_SZ 10240
#define B_SZ 8704
#define BOFF 20480
#define BYTESTRIDE 136

__global__ __launch_bounds__(256) void k_gemm(
    const float* __restrict__ gumbel,
    const float* __restrict__ bw3, const float* __restrict__ bb3,
    const float* __restrict__ sw3, const float* __restrict__ sb3)
{
    __shared__ __align__(16) char sbuf[BOFF + 2 * B_SZ];
    __shared__ int batch_s[128];
    __shared__ float bdiff_s[128];

    int t = threadIdx.x;
    int wid = t >> 5;
    int lane = t & 31;
    int expert = blockIdx.x >> 2;
    int tile = blockIdx.x & 3;
    int nbig = g_cnt[0];
    int cnt = expert ? (B - nbig) : nbig;
    int base = expert ? nbig : 0;
    int rbase = tile * 128;
    int rows = cnt - rbase;
    if (rows <= 0) return;
    if (rows > 128) rows = 128;
    int n0 = blockIdx.y * 128;

    const float* B3 = expert ? sb3 : bb3;

    if (t < 128) {
        int r = t < rows ? t : (rows - 1);
        batch_s[t] = g_perm[base + rbase + r];
        float2 bp = *(const float2*)(B3 + 2 * (n0 + t));
        bdiff_s[t] = bp.x - bp.y;
    }
    __syncthreads();

    float acc[4][4][4];
#pragma unroll
    for (int i = 0; i < 4; i++)
#pragma unroll
        for (int jj = 0; jj < 4; jj++)
#pragma unroll
            for (int r = 0; r < 4; r++) acc[i][jj][r] = 0.f;

    const uint32_t sb0 = smem_u32(sbuf);
    const int mbase = (wid >> 2) * 64;
    const int nbase = (wid & 3) * 32;
    const int lrow = lane & 15;
    const int lsel = lane >> 4;

    const int cr = t >> 1;
    const int ch = t & 1;
    const __nv_bfloat16* asrc = g_h3hi + (size_t)batch_s[cr] * D3 + ch * 16;
    const uint32_t adst = sb0 + cr * TSTRIDE + ch * 32;
    const int br = t >> 3;
    const int bs = t & 7;
    const __nv_bfloat16* bsrc = g_wd + (size_t)expert * D3 * NE + (size_t)br * NE + n0 + bs * 16;
    const uint32_t bdst = sb0 + BOFF + br * BSTRIDE + bs * 32;

#define ISSUE_CHUNK(stg, jj)                                             \
    do {                                                                 \
        uint32_t _ad = adst + (stg) * A_SZ;                              \
        uint32_t _bd = bdst + (stg) * B_SZ;                              \
        const __nv_bfloat16* _as = asrc + (jj) * 32;                     \
        const __nv_bfloat16* _bs = bsrc + (size_t)(jj) * 32 * NE;        \
        cp16(_ad, _as); cp16(_ad + 16, _as + 8);                         \
        cp16(_bd, _bs); cp16(_bd + 16, _bs + 8);                         \
        CP_COMMIT();                                                     \
    } while (0)

    ISSUE_CHUNK(0, 0);

#pragma unroll 1
    for (int j = 0; j < 32; j++) {
        int stg = j & 1;
        if (j < 31) {
            ISSUE_CHUNK(stg ^ 1, j + 1);
            CP_WAIT(1);
        } else {
            CP_WAIT(0);
        }
        __syncthreads();

        uint32_t abase = sb0 + stg * A_SZ;
        uint32_t bbase = sb0 + BOFF + stg * B_SZ;
#pragma unroll
        for (int ks = 0; ks < 2; ks++) {
            uint32_t bh[2][4];
#pragma unroll
            for (int bg = 0; bg < 2; bg++) {
                uint32_t addr = bbase
                    + (uint32_t)((ks * 16 + (lane & 7) + ((lane >> 4) << 3)) * BSTRIDE)
                    + (uint32_t)((nbase + bg * 16 + ((lane >> 3) & 1) * 8) * 2);
                ldm_x4_trans(bh[bg][0], bh[bg][1], bh[bg][2], bh[bg][3], addr);
            }
            uint32_t koff = (uint32_t)((ks * 16 + lsel * 8) * 2);
            uint32_t af[4][4];
#pragma unroll
            for (int mf = 0; mf < 4; mf++) {
                uint32_t rowoff = (uint32_t)((mbase + mf * 16 + lrow) * TSTRIDE) + koff;
                ldm_x4(af[mf][0], af[mf][1], af[mf][2], af[mf][3], abase + rowoff);
            }
#pragma unroll
            for (int mf = 0; mf < 4; mf++)
#pragma unroll
                for (int nf = 0; nf < 4; nf++) {
                    int bg = nf >> 1, h = nf & 1;
                    mma_bf16(acc[mf][nf], af[mf][0], af[mf][1], af[mf][2], af[mf][3],
                             bh[bg][h], bh[bg][2 + h]);
                }
        }
        __syncthreads();
    }

    // ---- epilogue ----
    int g = lane >> 2, tid4 = lane & 3;
#pragma unroll
    for (int mf = 0; mf < 4; mf++) {
#pragma unroll
        for (int h = 0; h < 2; h++) {
            int mrow = mbase + mf * 16 + g + h * 8;
            bool valid = (mrow < rows);
            int bat = batch_s[mrow];
            const float2* gpr = (const float2*)(gumbel + (size_t)bat * OUT2 + 2 * n0);
#pragma unroll
            for (int nf = 0; nf < 4; nf++) {
                int ncol = nbase + nf * 8 + 2 * tid4;
                float2 gA = gpr[ncol];
                float2 gB = gpr[ncol + 1];
                float m0 = acc[mf][nf][h * 2 + 0] + bdiff_s[ncol]     + (gA.x - gA.y);
                float m1 = acc[mf][nf][h * 2 + 1] + bdiff_s[ncol + 1] + (gB.x - gB.y);
                unsigned short v = (unsigned short)((m0 >= 0.f ? 1 : 0) | ((m1 >= 0.f ? 1 : 0) << 8));
                *(unsigned short*)(sbuf + mrow * BYTESTRIDE + ncol) = v;
                if (valid) {
                    if (fabsf(m0) < THRESH) {
                        int ix = atomicAdd(&g_fix_cnt, 1);
                        if (ix < FIXCAP)
                            g_fix[ix] = ((uint32_t)expert << 24) | ((uint32_t)bat << 15)
                                      | (uint32_t)(n0 + ncol);
                    }
                    if (fabsf(m1) < THRESH) {
                        int ix = atomicAdd(&g_fix_cnt, 1);
                        if (ix < FIXCAP)
                            g_fix[ix] = ((uint32_t)expert << 24) | ((uint32_t)bat << 15)
                                      | (uint32_t)(n0 + ncol + 1);
                    }
                }
            }
        }
    }
    __syncthreads();

#pragma unroll
    for (int pass = 0; pass < 8; pass++) {
        int idx = pass * 256 + t;
        int r = idx >> 4, seg = idx & 15;
        if (r < rows) {
            uint2 v = *(const uint2*)(sbuf + r * BYTESTRIDE + seg * 8);
            *(uint2*)(g_edges + (size_t)batch_s[r] * EPAD + n0 + seg * 8) = v;
        }
    }
}

// ---------------- kernel C2: exact fp32 fixup ----------------
__global__ __launch_bounds__(256) void k_fix(
    const float* __restrict__ gumbel,
    const float* __restrict__ bw3, const float* __restrict__ bb3,
    const float* __restrict__ sw3, const float* __restrict__ sb3)
{
    int n = g_fix_cnt;
    if (n > FIXCAP) n = FIXCAP;
    int nw = gridDim.x * 8;
    int w = blockIdx.x * 8 + (threadIdx.x >> 5);
    int lane = threadIdx.x & 31;
    for (int it = w; it < n; it += nw) {
        uint32_t v = g_fix[it];
        int ex = v >> 24;
        int bat = (v >> 15) & 511;
        int e = v & 32767;
        const float* W3 = ex ? sw3 : bw3;
        const float* B3 = ex ? sb3 : bb3;
        const float* h = g_h3f + (size_t)bat * D3;
        const float* wp = W3 + 2 * e;
        float a0 = 0.f, a1 = 0.f, a2 = 0.f, a3 = 0.f;
#pragma unroll 8
        for (int i = 0; i < 32; i++) {
            int k = lane + i * 32;
            float2 ww = *(const float2*)(wp + (size_t)k * OUT2);
            float p = h[k] * (ww.x - ww.y);
            if ((i & 3) == 0) a0 += p; else if ((i & 3) == 1) a1 += p;
            else if ((i & 3) == 2) a2 += p; else a3 += p;
        }
        float s = (a0 + a1) + (a2 + a3);
#pragma unroll
        for (int o = 16; o; o >>= 1) s += __shfl_xor_sync(0xFFFFFFFFu, s, o);
        if (lane == 0) {
            float2 g2 = *(const float2*)(gumbel + (size_t)bat * OUT2 + 2 * e);
            float m = s + (B3[2 * e] - B3[2 * e + 1]) + (g2.x - g2.y);
            g_edges[(size_t)bat * EPAD + e] = (m >= 0.f) ? 1 : 0;
        }
    }
}

// ---------------- kernel D: expand bits -> symmetric 256x256 fp32 ----------------
__global__ __launch_bounds__(256) void k_expand(float* __restrict__ out) {
    const int pi_ = blockIdx.y;
    int I0, J0;
    {
        const int pI[10] = {0,0,0,0,1,1,1,2,2,3};
        const int pJ[10] = {0,1,2,3,1,2,3,2,3,3};
        I0 = pI[pi_] * 64; J0 = pJ[pi_] * 64;
    }
    int b = blockIdx.x;
    __shared__ unsigned char s[64][68];
    const unsigned char* eb = g_edges + (size_t)b * EPAD;
    float* ob = out + (size_t)b * (NN * NN);
    int t = threadIdx.x;
    bool diag = (I0 == J0);

    int col = t & 63;
    int rg = t >> 6;
#pragma unroll 4
    for (int c = 0; c < 16; c++) {
        int il = rg * 16 + c;
        int i = I0 + il;
        int j = J0 + col;
        unsigned char v = 0;
        if (j > i) v = eb[(size_t)i * (511 - i) / 2 + (j - i - 1)];
        s[il][col] = v;
    }
    __syncthreads();

    int ilq = t >> 4;
    int jl = (t & 15) * 4;
#pragma unroll
    for (int p = 0; p < 4; p++) {
        int il = p * 16 + ilq;
        float4 v;
        if (diag) {
            int i = I0 + il;
            float vv[4];
#pragma unroll
            for (int c = 0; c < 4; c++) {
                int jj = J0 + jl + c;
                unsigned char u = (jj > i) ? s[il][jl + c] : ((jj < i) ? s[jl + c][il] : 0);
                vv[c] = (float)u;
            }
            v = make_float4(vv[0], vv[1], vv[2], vv[3]);
        } else {
            v = make_float4((float)s[il][jl], (float)s[il][jl + 1],
                            (float)s[il][jl + 2], (float)s[il][jl + 3]);
        }
        *(float4*)&ob[(I0 + il) * NN + J0 + jl] = v;
        if (!diag) {
            float4 w = make_float4((float)s[jl][il], (float)s[jl + 1][il],
                                   (float)s[jl + 2][il], (float)s[jl + 3][il]);
            *(float4*)&ob[(J0 + il) * NN + I0 + jl] = w;
        }
    }
}

// ---------------- launch ----------------
extern "C" void kernel_launch(void* const* d_in, const int* in_sizes, int n_in,
                              void* d_out, int out_size) {
    const float* x      = (const float*)d_in[0];
    const float* gumbel = (const float*)d_in[1];

    const float *bw[4], *bb[4], *sw[4], *sb[4];
    if (in_sizes[4] == 16384) {
        for (int l = 0; l < 4; l++) {
            bw[l] = (const float*)d_in[2 + 4 * l];
            bb[l] = (const float*)d_in[3 + 4 * l];
            sw[l] = (const float*)d_in[4 + 4 * l];
            sb[l] = (const float*)d_in[5 + 4 * l];
        }
    } else {
        for (int l = 0; l < 4; l++) {
            bw[l] = (const float*)d_in[2 + 2 * l];
            bb[l] = (const float*)d_in[3 + 2 * l];
            sw[l] = (const float*)d_in[10 + 2 * l];
            sb[l] = (const float*)d_in[11 + 2 * l];
        }
    }
    float* out = (float*)d_out;

    static bool s_init = false;
    static cudaStream_t s_side = 0;
    static cudaEvent_t ev_fork = 0, ev_w = 0;
    if (!s_init) {
        s_init = true;
        if (cudaStreamCreateWithFlags(&s_side, cudaStreamNonBlocking) != cudaSuccess) {
            s_side = 0;
        } else if (cudaEventCreateWithFlags(&ev_fork, cudaEventDisableTiming) != cudaSuccess ||
                   cudaEventCreateWithFlags(&ev_w, cudaEventDisableTiming) != cudaSuccess) {
            s_side = 0;
        }
    }

    if (s_side) {
        cudaEventRecord(ev_fork, 0);
        cudaStreamWaitEvent(s_side, ev_fork, 0);
        k_wdiff<<<dim3(1024, 2), 256, 0, s_side>>>(bw[3], sw[3]);
        cudaEventRecord(ev_w, s_side);
        k_group<<<1, B>>>(x);
        k_hidden<<<dim3(128, 2), 256>>>(x,
            bw[0], bb[0], bw[1], bb[1], bw[2], bb[2],
            sw[0], sb[0], sw[1], sb[1], sw[2], sb[2]);
        cudaStreamWaitEvent(0, ev_w, 0);
        k_gemm<<<dim3(8, 255), 256>>>(gumbel, bw[3], bb[3], sw[3], sb[3]);
    } else {
        k_group<<<1, B>>>(x);
        k_wdiff<<<dim3(1024, 2), 256>>>(bw[3], sw[3]);
        k_hidden<<<dim3(128, 2), 256>>>(x,
            bw[0], bb[0], bw[1], bb[1], bw[2], bb[2],
            sw[0], sb[0], sw[1], sb[1], sw[2], sb[2]);
        k_gemm<<<dim3(8, 255), 256>>>(gumbel, bw[3], bb[3], sw[3], sb[3]);
    }
    k_fix<<<296, 256>>>(gumbel, bw[3], bb[3], sw[3], sb[3]);
    k_expand<<<dim3(B, 10), 256>>>(out);
}

// round 16
// speedup vs baseline: 1.1421x; 1.0404x over previous
#include <cuda_runtime.h>
#include <cuda_bf16.h>
#include <cstdint>

#define B 512
#define COND 64
#define NN 256
#define NE 32640
#define OUT2 65280
#define D1 256
#define D2 512
#define D3 1024
#define EPAD 32768
#define FIXCAP (1 << 20)
#define THRESH 2e-4f

// ---------------- scratch ----------------
__device__ __nv_bfloat16 g_h3hi[B * D3];
__device__ float g_h3f[B * D3];
__device__ __nv_bfloat16 g_wd[2 * D3 * NE];    // 134 MB: bf16 weight diffs, K-MAJOR [ex][k][edge]
__device__ int g_perm[B];
__device__ int g_cnt[2];
__device__ unsigned char g_edges[B * EPAD];
__device__ int g_fix_cnt;
__device__ uint32_t g_fix[FIXCAP];

// ---------------- helpers ----------------
__device__ __forceinline__ uint32_t smem_u32(const void* p) {
    uint32_t a;
    asm("{ .reg .u64 t; cvta.to.shared.u64 t, %1; cvt.u32.u64 %0, t; }" : "=r"(a) : "l"(p));
    return a;
}
__device__ __forceinline__ void ldm_x4(uint32_t& r0, uint32_t& r1, uint32_t& r2, uint32_t& r3,
                                       uint32_t addr) {
    asm volatile("ldmatrix.sync.aligned.m8n8.x4.shared.b16 {%0,%1,%2,%3}, [%4];"
                 : "=r"(r0), "=r"(r1), "=r"(r2), "=r"(r3) : "r"(addr));
}
__device__ __forceinline__ void ldm_x4_trans(uint32_t& r0, uint32_t& r1, uint32_t& r2, uint32_t& r3,
                                             uint32_t addr) {
    asm volatile("ldmatrix.sync.aligned.m8n8.x4.trans.shared.b16 {%0,%1,%2,%3}, [%4];"
                 : "=r"(r0), "=r"(r1), "=r"(r2), "=r"(r3) : "r"(addr));
}
__device__ __forceinline__ void mma_bf16(float* c, uint32_t a0, uint32_t a1, uint32_t a2,
                                         uint32_t a3, uint32_t b0, uint32_t b1) {
    asm volatile(
        "mma.sync.aligned.m16n8k16.row.col.f32.bf16.bf16.f32 "
        "{%0,%1,%2,%3}, {%4,%5,%6,%7}, {%8,%9}, {%0,%1,%2,%3};"
        : "+f"(c[0]), "+f"(c[1]), "+f"(c[2]), "+f"(c[3])
        : "r"(a0), "r"(a1), "r"(a2), "r"(a3), "r"(b0), "r"(b1));
}
__device__ __forceinline__ void cp16(uint32_t dst, const void* src) {
    asm volatile("cp.async.cg.shared.global [%0], [%1], 16;" :: "r"(dst), "l"(src));
}
#define CP_COMMIT() asm volatile("cp.async.commit_group;" ::: "memory")
#define CP_WAIT(n)  asm volatile("cp.async.wait_group %0;" :: "n"(n) : "memory")

// ---------------- kernel A: partition by expert ----------------
__global__ void k_group(const float* __restrict__ x) {
    __shared__ int cnt[2];
    int t = threadIdx.x;
    if (t < 2) cnt[t] = 0;
    __syncthreads();
    int big = (x[t * COND] > 0.0f) ? 1 : 0;
    int p = atomicAdd(&cnt[big ? 0 : 1], 1);
    g_perm[big ? p : (B - 1 - p)] = t;
    __syncthreads();
    if (t == 0) { g_cnt[0] = cnt[0]; g_cnt[1] = cnt[1]; g_fix_cnt = 0; }
}

// ---------------- kernel W: W3 diffs -> bf16, K-MAJOR, edge-chunk range [c0, c1) ----------------
__global__ __launch_bounds__(256) void k_wdiff(
    const float* __restrict__ bw3, const float* __restrict__ sw3,
    int c0, int c1)
{
    int kr = blockIdx.x;
    int ex = blockIdx.y;
    const float* src = (ex ? sw3 : bw3) + (size_t)kr * OUT2;
    __nv_bfloat16* dst = g_wd + (size_t)ex * D3 * NE + (size_t)kr * NE;
    int t = threadIdx.x;
#pragma unroll 2
    for (int i = c0 + t; i < c1; i += 256) {
        const float4* s4 = (const float4*)(src + i * 16);
        float4 w0 = s4[0], w1 = s4[1], w2 = s4[2], w3v = s4[3];
        union { __nv_bfloat162 h[4]; uint4 v; } pk;
        pk.h[0] = __floats2bfloat162_rn(w0.x - w0.y, w0.z - w0.w);
        pk.h[1] = __floats2bfloat162_rn(w1.x - w1.y, w1.z - w1.w);
        pk.h[2] = __floats2bfloat162_rn(w2.x - w2.y, w2.z - w2.w);
        pk.h[3] = __floats2bfloat162_rn(w3v.x - w3v.y, w3v.z - w3v.w);
        *(uint4*)(dst + i * 8) = pk.v;
    }
}

// ---------------- kernel B: trunk, 2 batches/block, L3 quarter/block, grid (256, 4) ----------------
__global__ __launch_bounds__(256) void k_hidden(
    const float* __restrict__ x,
    const float* __restrict__ bw0, const float* __restrict__ bb0,
    const float* __restrict__ bw1, const float* __restrict__ bb1,
    const float* __restrict__ bw2, const float* __restrict__ bb2,
    const float* __restrict__ sw0, const float* __restrict__ sb0,
    const float* __restrict__ sw1, const float* __restrict__ sb1,
    const float* __restrict__ sw2, const float* __restrict__ sb2)
{
    __shared__ float xs[2][COND];
    __shared__ float h1s[2][D1];
    __shared__ float h2s[2][D2];
    __shared__ int bi[2];

    int t = threadIdx.x;
    int g = blockIdx.x;       // 0..255: 2-batch group
    int qh = blockIdx.y;      // 0..3: L3 quarter (256 neurons)
    if (t < 2) bi[t] = g_perm[g * 2 + t];
    __syncthreads();
    int nbig = g_cnt[0];

    for (int i = t; i < 2 * COND; i += 256) {
        int s = i >> 6, k = i & 63;
        xs[s][k] = x[bi[s] * COND + k];
    }
    __syncthreads();

    for (int ex = 0; ex < 2; ex++) {
        bool own[2]; bool anyown = false;
#pragma unroll
        for (int s = 0; s < 2; s++) {
            own[s] = (((g * 2 + s) < nbig ? 0 : 1) == ex);
            anyown |= own[s];
        }
        if (!anyown) continue;

        const float* W0 = ex ? sw0 : bw0; const float* B0 = ex ? sb0 : bb0;
        const float* W1 = ex ? sw1 : bw1; const float* B1 = ex ? sb1 : bb1;
        const float* W2 = ex ? sw2 : bw2; const float* B2 = ex ? sb2 : bb2;

        { // L1: 64 -> 256
            float a0 = 0.f, a1 = 0.f;
#pragma unroll 8
            for (int k = 0; k < COND; k++) {
                float w = W0[k * D1 + t];
                a0 = fmaf(xs[0][k], w, a0);
                a1 = fmaf(xs[1][k], w, a1);
            }
            float bb = B0[t];
            h1s[0][t] = fmaxf(a0 + bb, 0.f);
            h1s[1][t] = fmaxf(a1 + bb, 0.f);
        }
        __syncthreads();

        { // L2: 256 -> 512 (neurons t, t+256)
            float a00 = 0.f, a01 = 0.f, a10 = 0.f, a11 = 0.f;
#pragma unroll 8
            for (int k = 0; k < D1; k++) {
                float w0 = W1[k * D2 + t];
                float w1 = W1[k * D2 + t + 256];
                float h0 = h1s[0][k], h1 = h1s[1][k];
                a00 = fmaf(h0, w0, a00);
                a10 = fmaf(h1, w0, a10);
                a01 = fmaf(h0, w1, a01);
                a11 = fmaf(h1, w1, a11);
            }
            float b0v = B1[t], b1v = B1[t + 256];
            h2s[0][t]       = fmaxf(a00 + b0v, 0.f);
            h2s[1][t]       = fmaxf(a10 + b0v, 0.f);
            h2s[0][t + 256] = fmaxf(a01 + b1v, 0.f);
            h2s[1][t + 256] = fmaxf(a11 + b1v, 0.f);
        }
        __syncthreads();

        { // L3: 512 -> 256 (this block's quarter)
            int c = qh * 256 + t;
            float a0 = 0.f, a1 = 0.f;
#pragma unroll 8
            for (int k = 0; k < D2; k++) {
                float w = W2[k * D3 + c];
                a0 = fmaf(h2s[0][k], w, a0);
                a1 = fmaf(h2s[1][k], w, a1);
            }
            float bq = B2[c];
            if (own[0]) {
                float v = fmaxf(a0 + bq, 0.f);
                g_h3hi[bi[0] * D3 + c] = __float2bfloat16_rn(v);
                g_h3f[bi[0] * D3 + c] = v;
            }
            if (own[1]) {
                float v = fmaxf(a1 + bq, 0.f);
                g_h3hi[bi[1] * D3 + c] = __float2bfloat16_rn(v);
                g_h3f[bi[1] * D3 + c] = v;
            }
        }
        __syncthreads();
    }
}

// ---------------- kernel C: bf16 GEMM, k-major B via ldmatrix.trans ----------------
#define TSTRIDE 80
#define BSTRIDE 272
#define A_SZ 10240
#define B_SZ 8704
#define BOFF 20480
#define BYTESTRIDE 136

__global__ __launch_bounds__(256) void k_gemm(
    const float* __restrict__ gumbel,
    const float* __restrict__ bw3, const float* __restrict__ bb3,
    const float* __restrict__ sw3, const float* __restrict__ sb3,
    int yoff)
{
    __shared__ __align__(16) char sbuf[BOFF + 2 * B_SZ];
    __shared__ int batch_s[128];
    __shared__ float bdiff_s[128];

    int t = threadIdx.x;
    int wid = t >> 5;
    int lane = t & 31;
    int expert = blockIdx.x >> 2;
    int tile = blockIdx.x & 3;
    int nbig = g_cnt[0];
    int cnt = expert ? (B - nbig) : nbig;
    int base = expert ? nbig : 0;
    int rbase = tile * 128;
    int rows = cnt - rbase;
    if (rows <= 0) return;
    if (rows > 128) rows = 128;
    int n0 = (blockIdx.y + yoff) * 128;

    const float* B3 = expert ? sb3 : bb3;

    if (t < 128) {
        int r = t < rows ? t : (rows - 1);
        batch_s[t] = g_perm[base + rbase + r];
        float2 bp = *(const float2*)(B3 + 2 * (n0 + t));
        bdiff_s[t] = bp.x - bp.y;
    }
    __syncthreads();

    float acc[4][4][4];
#pragma unroll
    for (int i = 0; i < 4; i++)
#pragma unroll
        for (int jj = 0; jj < 4; jj++)
#pragma unroll
            for (int r = 0; r < 4; r++) acc[i][jj][r] = 0.f;

    const uint32_t sb0 = smem_u32(sbuf);
    const int mbase = (wid >> 2) * 64;
    const int nbase = (wid & 3) * 32;
    const int lrow = lane & 15;
    const int lsel = lane >> 4;

    const int cr = t >> 1;
    const int ch = t & 1;
    const __nv_bfloat16* asrc = g_h3hi + (size_t)batch_s[cr] * D3 + ch * 16;
    const uint32_t adst = sb0 + cr * TSTRIDE + ch * 32;
    const int br = t >> 3;
    const int bs = t & 7;
    const __nv_bfloat16* bsrc = g_wd + (size_t)expert * D3 * NE + (size_t)br * NE + n0 + bs * 16;
    const uint32_t bdst = sb0 + BOFF + br * BSTRIDE + bs * 32;

#define ISSUE_CHUNK(stg, jj)                                             \
    do {                                                                 \
        uint32_t _ad = adst + (stg) * A_SZ;                              \
        uint32_t _bd = bdst + (stg) * B_SZ;                              \
        const __nv_bfloat16* _as = asrc + (jj) * 32;                     \
        const __nv_bfloat16* _bs = bsrc + (size_t)(jj) * 32 * NE;        \
        cp16(_ad, _as); cp16(_ad + 16, _as + 8);                         \
        cp16(_bd, _bs); cp16(_bd + 16, _bs + 8);                         \
        CP_COMMIT();                                                     \
    } while (0)

    ISSUE_CHUNK(0, 0);

#pragma unroll 1
    for (int j = 0; j < 32; j++) {
        int stg = j & 1;
        if (j < 31) {
            ISSUE_CHUNK(stg ^ 1, j + 1);
            CP_WAIT(1);
        } else {
            CP_WAIT(0);
        }
        __syncthreads();

        uint32_t abase = sb0 + stg * A_SZ;
        uint32_t bbase = sb0 + BOFF + stg * B_SZ;
#pragma unroll
        for (int ks = 0; ks < 2; ks++) {
            uint32_t bh[2][4];
#pragma unroll
            for (int bg = 0; bg < 2; bg++) {
                uint32_t addr = bbase
                    + (uint32_t)((ks * 16 + (lane & 7) + ((lane >> 4) << 3)) * BSTRIDE)
                    + (uint32_t)((nbase + bg * 16 + ((lane >> 3) & 1) * 8) * 2);
                ldm_x4_trans(bh[bg][0], bh[bg][1], bh[bg][2], bh[bg][3], addr);
            }
            uint32_t koff = (uint32_t)((ks * 16 + lsel * 8) * 2);
            uint32_t af[4][4];
#pragma unroll
            for (int mf = 0; mf < 4; mf++) {
                uint32_t rowoff = (uint32_t)((mbase + mf * 16 + lrow) * TSTRIDE) + koff;
                ldm_x4(af[mf][0], af[mf][1], af[mf][2], af[mf][3], abase + rowoff);
            }
#pragma unroll
            for (int mf = 0; mf < 4; mf++)
#pragma unroll
                for (int nf = 0; nf < 4; nf++) {
                    int bg = nf >> 1, h = nf & 1;
                    mma_bf16(acc[mf][nf], af[mf][0], af[mf][1], af[mf][2], af[mf][3],
                             bh[bg][h], bh[bg][2 + h]);
                }
        }
        __syncthreads();
    }

    // ---- epilogue ----
    int g = lane >> 2, tid4 = lane & 3;
#pragma unroll
    for (int mf = 0; mf < 4; mf++) {
#pragma unroll
        for (int h = 0; h < 2; h++) {
            int mrow = mbase + mf * 16 + g + h * 8;
            bool valid = (mrow < rows);
            int bat = batch_s[mrow];
            const float2* gpr = (const float2*)(gumbel + (size_t)bat * OUT2 + 2 * n0);
#pragma unroll
            for (int nf = 0; nf < 4; nf++) {
                int ncol = nbase + nf * 8 + 2 * tid4;
                float2 gA = gpr[ncol];
                float2 gB = gpr[ncol + 1];
                float m0 = acc[mf][nf][h * 2 + 0] + bdiff_s[ncol]     + (gA.x - gA.y);
                float m1 = acc[mf][nf][h * 2 + 1] + bdiff_s[ncol + 1] + (gB.x - gB.y);
                unsigned short v = (unsigned short)((m0 >= 0.f ? 1 : 0) | ((m1 >= 0.f ? 1 : 0) << 8));
                *(unsigned short*)(sbuf + mrow * BYTESTRIDE + ncol) = v;
                if (valid) {
                    if (fabsf(m0) < THRESH) {
                        int ix = atomicAdd(&g_fix_cnt, 1);
                        if (ix < FIXCAP)
                            g_fix[ix] = ((uint32_t)expert << 24) | ((uint32_t)bat << 15)
                                      | (uint32_t)(n0 + ncol);
                    }
                    if (fabsf(m1) < THRESH) {
                        int ix = atomicAdd(&g_fix_cnt, 1);
                        if (ix < FIXCAP)
                            g_fix[ix] = ((uint32_t)expert << 24) | ((uint32_t)bat << 15)
                                      | (uint32_t)(n0 + ncol + 1);
                    }
                }
            }
        }
    }
    __syncthreads();

#pragma unroll
    for (int pass = 0; pass < 8; pass++) {
        int idx = pass * 256 + t;
        int r = idx >> 4, seg = idx & 15;
        if (r < rows) {
            uint2 v = *(const uint2*)(sbuf + r * BYTESTRIDE + seg * 8);
            *(uint2*)(g_edges + (size_t)batch_s[r] * EPAD + n0 + seg * 8) = v;
        }
    }
}

// ---------------- kernel C2: exact fp32 fixup ----------------
__global__ __launch_bounds__(256) void k_fix(
    const float* __restrict__ gumbel,
    const float* __restrict__ bw3, const float* __restrict__ bb3,
    const float* __restrict__ sw3, const float* __restrict__ sb3)
{
    int n = g_fix_cnt;
    if (n > FIXCAP) n = FIXCAP;
    int nw = gridDim.x * 8;
    int w = blockIdx.x * 8 + (threadIdx.x >> 5);
    int lane = threadIdx.x & 31;
    for (int it = w; it < n; it += nw) {
        uint32_t v = g_fix[it];
        int ex = v >> 24;
        int bat = (v >> 15) & 511;
        int e = v & 32767;
        const float* W3 = ex ? sw3 : bw3;
        const float* B3 = ex ? sb3 : bb3;
        const float* h = g_h3f + (size_t)bat * D3;
        const float* wp = W3 + 2 * e;
        float a0 = 0.f, a1 = 0.f, a2 = 0.f, a3 = 0.f;
#pragma unroll 8
        for (int i = 0; i < 32; i++) {
            int k = lane + i * 32;
            float2 ww = *(const float2*)(wp + (size_t)k * OUT2);
            float p = h[k] * (ww.x - ww.y);
            if ((i & 3) == 0) a0 += p; else if ((i & 3) == 1) a1 += p;
            else if ((i & 3) == 2) a2 += p; else a3 += p;
        }
        float s = (a0 + a1) + (a2 + a3);
#pragma unroll
        for (int o = 16; o; o >>= 1) s += __shfl_xor_sync(0xFFFFFFFFu, s, o);
        if (lane == 0) {
            float2 g2 = *(const float2*)(gumbel + (size_t)bat * OUT2 + 2 * e);
            float m = s + (B3[2 * e] - B3[2 * e + 1]) + (g2.x - g2.y);
            g_edges[(size_t)bat * EPAD + e] = (m >= 0.f) ? 1 : 0;
        }
    }
}

// ---------------- kernel D: expand bits -> symmetric 256x256 fp32 ----------------
__global__ __launch_bounds__(256) void k_expand(float* __restrict__ out) {
    const int pi_ = blockIdx.y;
    int I0, J0;
    {
        const int pI[10] = {0,0,0,0,1,1,1,2,2,3};
        const int pJ[10] = {0,1,2,3,1,2,3,2,3,3};
        I0 = pI[pi_] * 64; J0 = pJ[pi_] * 64;
    }
    int b = blockIdx.x;
    __shared__ unsigned char s[64][68];
    const unsigned char* eb = g_edges + (size_t)b * EPAD;
    float* ob = out + (size_t)b * (NN * NN);
    int t = threadIdx.x;
    bool diag = (I0 == J0);

    int col = t & 63;
    int rg = t >> 6;
#pragma unroll 4
    for (int c = 0; c < 16; c++) {
        int il = rg * 16 + c;
        int i = I0 + il;
        int j = J0 + col;
        unsigned char v = 0;
        if (j > i) v = eb[(size_t)i * (511 - i) / 2 + (j - i - 1)];
        s[il][col] = v;
    }
    __syncthreads();

    int ilq = t >> 4;
    int jl = (t & 15) * 4;
#pragma unroll
    for (int p = 0; p < 4; p++) {
        int il = p * 16 + ilq;
        float4 v;
        if (diag) {
            int i = I0 + il;
            float vv[4];
#pragma unroll
            for (int c = 0; c < 4; c++) {
                int jj = J0 + jl + c;
                unsigned char u = (jj > i) ? s[il][jl + c] : ((jj < i) ? s[jl + c][il] : 0);
                vv[c] = (float)u;
            }
            v = make_float4(vv[0], vv[1], vv[2], vv[3]);
        } else {
            v = make_float4((float)s[il][jl], (float)s[il][jl + 1],
                            (float)s[il][jl + 2], (float)s[il][jl + 3]);
        }
        *(float4*)&ob[(I0 + il) * NN + J0 + jl] = v;
        if (!diag) {
            float4 w = make_float4((float)s[jl][il], (float)s[jl + 1][il],
                                   (float)s[jl + 2][il], (float)s[jl + 3][il]);
            *(float4*)&ob[(J0 + il) * NN + I0 + jl] = w;
        }
    }
}

// ---------------- launch ----------------
extern "C" void kernel_launch(void* const* d_in, const int* in_sizes, int n_in,
                              void* d_out, int out_size) {
    const float* x      = (const float*)d_in[0];
    const float* gumbel = (const float*)d_in[1];

    const float *bw[4], *bb[4], *sw[4], *sb[4];
    if (in_sizes[4] == 16384) {
        for (int l = 0; l < 4; l++) {
            bw[l] = (const float*)d_in[2 + 4 * l];
            bb[l] = (const float*)d_in[3 + 4 * l];
            sw[l] = (const float*)d_in[4 + 4 * l];
            sb[l] = (const float*)d_in[5 + 4 * l];
        }
    } else {
        for (int l = 0; l < 4; l++) {
            bw[l] = (const float*)d_in[2 + 2 * l];
            bb[l] = (const float*)d_in[3 + 2 * l];
            sw[l] = (const float*)d_in[10 + 2 * l];
            sb[l] = (const float*)d_in[11 + 2 * l];
        }
    }
    float* out = (float*)d_out;

    static bool s_init = false;
    static cudaStream_t s_side = 0;
    static cudaEvent_t ev_fork = 0, ev_w0 = 0, ev_w1 = 0;
    if (!s_init) {
        s_init = true;
        if (cudaStreamCreateWithFlags(&s_side, cudaStreamNonBlocking) != cudaSuccess) {
            s_side = 0;
        } else if (cudaEventCreateWithFlags(&ev_fork, cudaEventDisableTiming) != cudaSuccess ||
                   cudaEventCreateWithFlags(&ev_w0, cudaEventDisableTiming) != cudaSuccess ||
                   cudaEventCreateWithFlags(&ev_w1, cudaEventDisableTiming) != cudaSuccess) {
            s_side = 0;
        }
    }

    if (s_side) {
        cudaEventRecord(ev_fork, 0);
        cudaStreamWaitEvent(s_side, ev_fork, 0);
        // side stream: wdiff in two edge halves
        k_wdiff<<<dim3(1024, 2), 256, 0, s_side>>>(bw[3], sw[3], 0, 2048);
        cudaEventRecord(ev_w0, s_side);
        k_wdiff<<<dim3(1024, 2), 256, 0, s_side>>>(bw[3], sw[3], 2048, 4080);
        cudaEventRecord(ev_w1, s_side);
        // main stream: trunk, then gemm halves gated by wdiff halves
        k_group<<<1, B>>>(x);
        k_hidden<<<dim3(256, 4), 256>>>(x,
            bw[0], bb[0], bw[1], bb[1], bw[2], bb[2],
            sw[0], sb[0], sw[1], sb[1], sw[2], sb[2]);
        cudaStreamWaitEvent(0, ev_w0, 0);
        k_gemm<<<dim3(8, 128), 256>>>(gumbel, bw[3], bb[3], sw[3], sb[3], 0);
        cudaStreamWaitEvent(0, ev_w1, 0);
        k_gemm<<<dim3(8, 127), 256>>>(gumbel, bw[3], bb[3], sw[3], sb[3], 128);
    } else {
        k_group<<<1, B>>>(x);
        k_wdiff<<<dim3(1024, 2), 256>>>(bw[3], sw[3], 0, 4080);
        k_hidden<<<dim3(256, 4), 256>>>(x,
            bw[0], bb[0], bw[1], bb[1], bw[2], bb[2],
            sw[0], sb[0], sw[1], sb[1], sw[2], sb[2]);
        k_gemm<<<dim3(8, 255), 256>>>(gumbel, bw[3], bb[3], sw[3], sb[3], 0);
    }
    k_fix<<<296, 256>>>(gumbel, bw[3], bb[3], sw[3], sb[3]);
    k_expand<<<dim3(B, 10), 256>>>(out);
}

// round 17
// speedup vs baseline: 1.2911x; 1.1305x over previous
#include <cuda_runtime.h>
#include <cuda_bf16.h>
#include <cstdint>

#define B 512
#define COND 64
#define NN 256
#define NE 32640
#define OUT2 65280
#define D1 256
#define D2 512
#define D3 1024
#define EPAD 32768
#define FIXCAP (1 << 20)
#define THRESH 2e-4f

// ---------------- scratch ----------------
__device__ __nv_bfloat16 g_h3hi[B * D3];
__device__ float g_h3f[B * D3];
__device__ __nv_bfloat16 g_wd[2 * D3 * NE];    // 134 MB: bf16 weight diffs, K-MAJOR [ex][k][edge]
__device__ int g_perm[B];
__device__ int g_cnt[2];
__device__ unsigned char g_edges[B * EPAD];
__device__ int g_fix_cnt;
__device__ uint32_t g_fix[FIXCAP];

// ---------------- helpers ----------------
__device__ __forceinline__ uint32_t smem_u32(const void* p) {
    uint32_t a;
    asm("{ .reg .u64 t; cvta.to.shared.u64 t, %1; cvt.u32.u64 %0, t; }" : "=r"(a) : "l"(p));
    return a;
}
__device__ __forceinline__ void ldm_x4(uint32_t& r0, uint32_t& r1, uint32_t& r2, uint32_t& r3,
                                       uint32_t addr) {
    asm volatile("ldmatrix.sync.aligned.m8n8.x4.shared.b16 {%0,%1,%2,%3}, [%4];"
                 : "=r"(r0), "=r"(r1), "=r"(r2), "=r"(r3) : "r"(addr));
}
__device__ __forceinline__ void ldm_x4_trans(uint32_t& r0, uint32_t& r1, uint32_t& r2, uint32_t& r3,
                                             uint32_t addr) {
    asm volatile("ldmatrix.sync.aligned.m8n8.x4.trans.shared.b16 {%0,%1,%2,%3}, [%4];"
                 : "=r"(r0), "=r"(r1), "=r"(r2), "=r"(r3) : "r"(addr));
}
__device__ __forceinline__ void mma_bf16(float* c, uint32_t a0, uint32_t a1, uint32_t a2,
                                         uint32_t a3, uint32_t b0, uint32_t b1) {
    asm volatile(
        "mma.sync.aligned.m16n8k16.row.col.f32.bf16.bf16.f32 "
        "{%0,%1,%2,%3}, {%4,%5,%6,%7}, {%8,%9}, {%0,%1,%2,%3};"
        : "+f"(c[0]), "+f"(c[1]), "+f"(c[2]), "+f"(c[3])
        : "r"(a0), "r"(a1), "r"(a2), "r"(a3), "r"(b0), "r"(b1));
}
__device__ __forceinline__ void cp16(uint32_t dst, const void* src) {
    asm volatile("cp.async.cg.shared.global [%0], [%1], 16;" :: "r"(dst), "l"(src));
}
#define CP_COMMIT() asm volatile("cp.async.commit_group;" ::: "memory")
#define CP_WAIT(n)  asm volatile("cp.async.wait_group %0;" :: "n"(n) : "memory")

// ---------------- kernel A: partition by expert ----------------
__global__ void k_group(const float* __restrict__ x) {
    __shared__ int cnt[2];
    int t = threadIdx.x;
    if (t < 2) cnt[t] = 0;
    __syncthreads();
    int big = (x[t * COND] > 0.0f) ? 1 : 0;
    int p = atomicAdd(&cnt[big ? 0 : 1], 1);
    g_perm[big ? p : (B - 1 - p)] = t;
    __syncthreads();
    if (t == 0) { g_cnt[0] = cnt[0]; g_cnt[1] = cnt[1]; g_fix_cnt = 0; }
}

// ---------------- kernel W: W3 diffs -> bf16, K-MAJOR (streaming) ----------------
__global__ __launch_bounds__(256) void k_wdiff(
    const float* __restrict__ bw3, const float* __restrict__ sw3)
{
    int kr = blockIdx.x;
    int ex = blockIdx.y;
    const float* src = (ex ? sw3 : bw3) + (size_t)kr * OUT2;
    __nv_bfloat16* dst = g_wd + (size_t)ex * D3 * NE + (size_t)kr * NE;
    int t = threadIdx.x;
#pragma unroll 2
    for (int i = t; i < 4080; i += 256) {
        const float4* s4 = (const float4*)(src + i * 16);
        float4 w0 = s4[0], w1 = s4[1], w2 = s4[2], w3v = s4[3];
        union { __nv_bfloat162 h[4]; uint4 v; } pk;
        pk.h[0] = __floats2bfloat162_rn(w0.x - w0.y, w0.z - w0.w);
        pk.h[1] = __floats2bfloat162_rn(w1.x - w1.y, w1.z - w1.w);
        pk.h[2] = __floats2bfloat162_rn(w2.x - w2.y, w2.z - w2.w);
        pk.h[3] = __floats2bfloat162_rn(w3v.x - w3v.y, w3v.z - w3v.w);
        *(uint4*)(dst + i * 8) = pk.v;
    }
}

// ---------------- kernel B: trunk, 2 batches/block, L3 quarter/block, grid (256, 4) ----------------
__global__ __launch_bounds__(256) void k_hidden(
    const float* __restrict__ x,
    const float* __restrict__ bw0, const float* __restrict__ bb0,
    const float* __restrict__ bw1, const float* __restrict__ bb1,
    const float* __restrict__ bw2, const float* __restrict__ bb2,
    const float* __restrict__ sw0, const float* __restrict__ sb0,
    const float* __restrict__ sw1, const float* __restrict__ sb1,
    const float* __restrict__ sw2, const float* __restrict__ sb2)
{
    __shared__ float xs[2][COND];
    __shared__ float h1s[2][D1];
    __shared__ float h2s[2][D2];
    __shared__ int bi[2];

    int t = threadIdx.x;
    int g = blockIdx.x;
    int qh = blockIdx.y;
    if (t < 2) bi[t] = g_perm[g * 2 + t];
    __syncthreads();
    int nbig = g_cnt[0];

    for (int i = t; i < 2 * COND; i += 256) {
        int s = i >> 6, k = i & 63;
        xs[s][k] = x[bi[s] * COND + k];
    }
    __syncthreads();

    for (int ex = 0; ex < 2; ex++) {
        bool own[2]; bool anyown = false;
#pragma unroll
        for (int s = 0; s < 2; s++) {
            own[s] = (((g * 2 + s) < nbig ? 0 : 1) == ex);
            anyown |= own[s];
        }
        if (!anyown) continue;

        const float* W0 = ex ? sw0 : bw0; const float* B0 = ex ? sb0 : bb0;
        const float* W1 = ex ? sw1 : bw1; const float* B1 = ex ? sb1 : bb1;
        const float* W2 = ex ? sw2 : bw2; const float* B2 = ex ? sb2 : bb2;

        { // L1: 64 -> 256
            float a0 = 0.f, a1 = 0.f;
#pragma unroll 8
            for (int k = 0; k < COND; k++) {
                float w = W0[k * D1 + t];
                a0 = fmaf(xs[0][k], w, a0);
                a1 = fmaf(xs[1][k], w, a1);
            }
            float bb = B0[t];
            h1s[0][t] = fmaxf(a0 + bb, 0.f);
            h1s[1][t] = fmaxf(a1 + bb, 0.f);
        }
        __syncthreads();

        { // L2: 256 -> 512
            float a00 = 0.f, a01 = 0.f, a10 = 0.f, a11 = 0.f;
#pragma unroll 8
            for (int k = 0; k < D1; k++) {
                float w0 = W1[k * D2 + t];
                float w1 = W1[k * D2 + t + 256];
                float h0 = h1s[0][k], h1 = h1s[1][k];
                a00 = fmaf(h0, w0, a00);
                a10 = fmaf(h1, w0, a10);
                a01 = fmaf(h0, w1, a01);
                a11 = fmaf(h1, w1, a11);
            }
            float b0v = B1[t], b1v = B1[t + 256];
            h2s[0][t]       = fmaxf(a00 + b0v, 0.f);
            h2s[1][t]       = fmaxf(a10 + b0v, 0.f);
            h2s[0][t + 256] = fmaxf(a01 + b1v, 0.f);
            h2s[1][t + 256] = fmaxf(a11 + b1v, 0.f);
        }
        __syncthreads();

        { // L3: 512 -> 256 (this block's quarter)
            int c = qh * 256 + t;
            float a0 = 0.f, a1 = 0.f;
#pragma unroll 8
            for (int k = 0; k < D2; k++) {
                float w = W2[k * D3 + c];
                a0 = fmaf(h2s[0][k], w, a0);
                a1 = fmaf(h2s[1][k], w, a1);
            }
            float bq = B2[c];
            if (own[0]) {
                float v = fmaxf(a0 + bq, 0.f);
                g_h3hi[bi[0] * D3 + c] = __float2bfloat16_rn(v);
                g_h3f[bi[0] * D3 + c] = v;
            }
            if (own[1]) {
                float v = fmaxf(a1 + bq, 0.f);
                g_h3hi[bi[1] * D3 + c] = __float2bfloat16_rn(v);
                g_h3f[bi[1] * D3 + c] = v;
            }
        }
        __syncthreads();
    }
}

// ---------------- kernel C: bf16 GEMM, k-major B via ldmatrix.trans ----------------
#define TSTRIDE 80
#define BSTRIDE 272
#define A_SZ 10240
#define B_SZ 8704
#define BOFF 20480
#define BYTESTRIDE 136

__global__ __launch_bounds__(256) void k_gemm(
    const float* __restrict__ gumbel,
    const float* __restrict__ bw3, const float* __restrict__ bb3,
    const float* __restrict__ sw3, const float* __restrict__ sb3)
{
    __shared__ __align__(16) char sbuf[BOFF + 2 * B_SZ];
    __shared__ int batch_s[128];
    __shared__ float bdiff_s[128];

    int t = threadIdx.x;
    int wid = t >> 5;
    int lane = t & 31;
    int expert = blockIdx.x >> 2;
    int tile = blockIdx.x & 3;
    int nbig = g_cnt[0];
    int cnt = expert ? (B - nbig) : nbig;
    int base = expert ? nbig : 0;
    int rbase = tile * 128;
    int rows = cnt - rbase;
    if (rows <= 0) return;
    if (rows > 128) rows = 128;
    int n0 = blockIdx.y * 128;

    const float* B3 = expert ? sb3 : bb3;

    if (t < 128) {
        int r = t < rows ? t : (rows - 1);
        batch_s[t] = g_perm[base + rbase + r];
        float2 bp = *(const float2*)(B3 + 2 * (n0 + t));
        bdiff_s[t] = bp.x - bp.y;
    }
    __syncthreads();

    float acc[4][4][4];
#pragma unroll
    for (int i = 0; i < 4; i++)
#pragma unroll
        for (int jj = 0; jj < 4; jj++)
#pragma unroll
            for (int r = 0; r < 4; r++) acc[i][jj][r] = 0.f;

    const uint32_t sb0 = smem_u32(sbuf);
    const int mbase = (wid >> 2) * 64;
    const int nbase = (wid & 3) * 32;
    const int lrow = lane & 15;
    const int lsel = lane >> 4;

    const int cr = t >> 1;
    const int ch = t & 1;
    const __nv_bfloat16* asrc = g_h3hi + (size_t)batch_s[cr] * D3 + ch * 16;
    const uint32_t adst = sb0 + cr * TSTRIDE + ch * 32;
    const int br = t >> 3;
    const int bs = t & 7;
    const __nv_bfloat16* bsrc = g_wd + (size_t)expert * D3 * NE + (size_t)br * NE + n0 + bs * 16;
    const uint32_t bdst = sb0 + BOFF + br * BSTRIDE + bs * 32;

#define ISSUE_CHUNK(stg, jj)                                             \
    do {                                                                 \
        uint32_t _ad = adst + (stg) * A_SZ;                              \
        uint32_t _bd = bdst + (stg) * B_SZ;                              \
        const __nv_bfloat16* _as = asrc + (jj) * 32;                     \
        const __nv_bfloat16* _bs = bsrc + (size_t)(jj) * 32 * NE;        \
        cp16(_ad, _as); cp16(_ad + 16, _as + 8);                         \
        cp16(_bd, _bs); cp16(_bd + 16, _bs + 8);                         \
        CP_COMMIT();                                                     \
    } while (0)

    ISSUE_CHUNK(0, 0);

#pragma unroll 1
    for (int j = 0; j < 32; j++) {
        int stg = j & 1;
        if (j < 31) {
            ISSUE_CHUNK(stg ^ 1, j + 1);
            CP_WAIT(1);
        } else {
            CP_WAIT(0);
        }
        __syncthreads();

        uint32_t abase = sb0 + stg * A_SZ;
        uint32_t bbase = sb0 + BOFF + stg * B_SZ;
#pragma unroll
        for (int ks = 0; ks < 2; ks++) {
            uint32_t bh[2][4];
#pragma unroll
            for (int bg = 0; bg < 2; bg++) {
                uint32_t addr = bbase
                    + (uint32_t)((ks * 16 + (lane & 7) + ((lane >> 4) << 3)) * BSTRIDE)
                    + (uint32_t)((nbase + bg * 16 + ((lane >> 3) & 1) * 8) * 2);
                ldm_x4_trans(bh[bg][0], bh[bg][1], bh[bg][2], bh[bg][3], addr);
            }
            uint32_t koff = (uint32_t)((ks * 16 + lsel * 8) * 2);
            uint32_t af[4][4];
#pragma unroll
            for (int mf = 0; mf < 4; mf++) {
                uint32_t rowoff = (uint32_t)((mbase + mf * 16 + lrow) * TSTRIDE) + koff;
                ldm_x4(af[mf][0], af[mf][1], af[mf][2], af[mf][3], abase + rowoff);
            }
#pragma unroll
            for (int mf = 0; mf < 4; mf++)
#pragma unroll
                for (int nf = 0; nf < 4; nf++) {
                    int bg = nf >> 1, h = nf & 1;
                    mma_bf16(acc[mf][nf], af[mf][0], af[mf][1], af[mf][2], af[mf][3],
                             bh[bg][h], bh[bg][2 + h]);
                }
        }
        __syncthreads();
    }

    // ---- epilogue ----
    int g = lane >> 2, tid4 = lane & 3;
#pragma unroll
    for (int mf = 0; mf < 4; mf++) {
#pragma unroll
        for (int h = 0; h < 2; h++) {
            int mrow = mbase + mf * 16 + g + h * 8;
            bool valid = (mrow < rows);
            int bat = batch_s[mrow];
            const float2* gpr = (const float2*)(gumbel + (size_t)bat * OUT2 + 2 * n0);
#pragma unroll
            for (int nf = 0; nf < 4; nf++) {
                int ncol = nbase + nf * 8 + 2 * tid4;
                float2 gA = gpr[ncol];
                float2 gB = gpr[ncol + 1];
                float m0 = acc[mf][nf][h * 2 + 0] + bdiff_s[ncol]     + (gA.x - gA.y);
                float m1 = acc[mf][nf][h * 2 + 1] + bdiff_s[ncol + 1] + (gB.x - gB.y);
                unsigned short v = (unsigned short)((m0 >= 0.f ? 1 : 0) | ((m1 >= 0.f ? 1 : 0) << 8));
                *(unsigned short*)(sbuf + mrow * BYTESTRIDE + ncol) = v;
                if (valid) {
                    if (fabsf(m0) < THRESH) {
                        int ix = atomicAdd(&g_fix_cnt, 1);
                        if (ix < FIXCAP)
                            g_fix[ix] = ((uint32_t)expert << 24) | ((uint32_t)bat << 15)
                                      | (uint32_t)(n0 + ncol);
                    }
                    if (fabsf(m1) < THRESH) {
                        int ix = atomicAdd(&g_fix_cnt, 1);
                        if (ix < FIXCAP)
                            g_fix[ix] = ((uint32_t)expert << 24) | ((uint32_t)bat << 15)
                                      | (uint32_t)(n0 + ncol + 1);
                    }
                }
            }
        }
    }
    __syncthreads();

#pragma unroll
    for (int pass = 0; pass < 8; pass++) {
        int idx = pass * 256 + t;
        int r = idx >> 4, seg = idx & 15;
        if (r < rows) {
            uint2 v = *(const uint2*)(sbuf + r * BYTESTRIDE + seg * 8);
            *(uint2*)(g_edges + (size_t)batch_s[r] * EPAD + n0 + seg * 8) = v;
        }
    }
}

// ---------------- kernel C2: exact fp32 fixup ----------------
__global__ __launch_bounds__(256) void k_fix(
    const float* __restrict__ gumbel,
    const float* __restrict__ bw3, const float* __restrict__ bb3,
    const float* __restrict__ sw3, const float* __restrict__ sb3)
{
    int n = g_fix_cnt;
    if (n > FIXCAP) n = FIXCAP;
    int nw = gridDim.x * 8;
    int w = blockIdx.x * 8 + (threadIdx.x >> 5);
    int lane = threadIdx.x & 31;
    for (int it = w; it < n; it += nw) {
        uint32_t v = g_fix[it];
        int ex = v >> 24;
        int bat = (v >> 15) & 511;
        int e = v & 32767;
        const float* W3 = ex ? sw3 : bw3;
        const float* B3 = ex ? sb3 : bb3;
        const float* h = g_h3f + (size_t)bat * D3;
        const float* wp = W3 + 2 * e;
        float a0 = 0.f, a1 = 0.f, a2 = 0.f, a3 = 0.f;
#pragma unroll 8
        for (int i = 0; i < 32; i++) {
            int k = lane + i * 32;
            float2 ww = *(const float2*)(wp + (size_t)k * OUT2);
            float p = h[k] * (ww.x - ww.y);
            if ((i & 3) == 0) a0 += p; else if ((i & 3) == 1) a1 += p;
            else if ((i & 3) == 2) a2 += p; else a3 += p;
        }
        float s = (a0 + a1) + (a2 + a3);
#pragma unroll
        for (int o = 16; o; o >>= 1) s += __shfl_xor_sync(0xFFFFFFFFu, s, o);
        if (lane == 0) {
            float2 g2 = *(const float2*)(gumbel + (size_t)bat * OUT2 + 2 * e);
            float m = s + (B3[2 * e] - B3[2 * e + 1]) + (g2.x - g2.y);
            g_edges[(size_t)bat * EPAD + e] = (m >= 0.f) ? 1 : 0;
        }
    }
}

// ---------------- kernel D: expand bits -> symmetric 256x256 fp32 ----------------
__global__ __launch_bounds__(256) void k_expand(float* __restrict__ out) {
    const int pi_ = blockIdx.y;
    int I0, J0;
    {
        const int pI[10] = {0,0,0,0,1,1,1,2,2,3};
        const int pJ[10] = {0,1,2,3,1,2,3,2,3,3};
        I0 = pI[pi_] * 64; J0 = pJ[pi_] * 64;
    }
    int b = blockIdx.x;
    __shared__ unsigned char s[64][68];
    const unsigned char* eb = g_edges + (size_t)b * EPAD;
    float* ob = out + (size_t)b * (NN * NN);
    int t = threadIdx.x;
    bool diag = (I0 == J0);

    int col = t & 63;
    int rg = t >> 6;
#pragma unroll 4
    for (int c = 0; c < 16; c++) {
        int il = rg * 16 + c;
        int i = I0 + il;
        int j = J0 + col;
        unsigned char v = 0;
        if (j > i) v = eb[(size_t)i * (511 - i) / 2 + (j - i - 1)];
        s[il][col] = v;
    }
    __syncthreads();

    int ilq = t >> 4;
    int jl = (t & 15) * 4;
#pragma unroll
    for (int p = 0; p < 4; p++) {
        int il = p * 16 + ilq;
        float4 v;
        if (diag) {
            int i = I0 + il;
            float vv[4];
#pragma unroll
            for (int c = 0; c < 4; c++) {
                int jj = J0 + jl + c;
                unsigned char u = (jj > i) ? s[il][jl + c] : ((jj < i) ? s[jl + c][il] : 0);
                vv[c] = (float)u;
            }
            v = make_float4(vv[0], vv[1], vv[2], vv[3]);
        } else {
            v = make_float4((float)s[il][jl], (float)s[il][jl + 1],
                            (float)s[il][jl + 2], (float)s[il][jl + 3]);
        }
        *(float4*)&ob[(I0 + il) * NN + J0 + jl] = v;
        if (!diag) {
            float4 w = make_float4((float)s[jl][il], (float)s[jl + 1][il],
                                   (float)s[jl + 2][il], (float)s[jl + 3][il]);
            *(float4*)&ob[(J0 + il) * NN + I0 + jl] = w;
        }
    }
}

// ---------------- launch ----------------
extern "C" void kernel_launch(void* const* d_in, const int* in_sizes, int n_in,
                              void* d_out, int out_size) {
    const float* x      = (const float*)d_in[0];
    const float* gumbel = (const float*)d_in[1];

    const float *bw[4], *bb[4], *sw[4], *sb[4];
    if (in_sizes[4] == 16384) {
        for (int l = 0; l < 4; l++) {
            bw[l] = (const float*)d_in[2 + 4 * l];
            bb[l] = (const float*)d_in[3 + 4 * l];
            sw[l] = (const float*)d_in[4 + 4 * l];
            sb[l] = (const float*)d_in[5 + 4 * l];
        }
    } else {
        for (int l = 0; l < 4; l++) {
            bw[l] = (const float*)d_in[2 + 2 * l];
            bb[l] = (const float*)d_in[3 + 2 * l];
            sw[l] = (const float*)d_in[10 + 2 * l];
            sb[l] = (const float*)d_in[11 + 2 * l];
        }
    }
    float* out = (float*)d_out;

    static bool s_init = false;
    static cudaStream_t s_side = 0;
    static cudaEvent_t ev_fork = 0, ev_w = 0;
    if (!s_init) {
        s_init = true;
        if (cudaStreamCreateWithFlags(&s_side, cudaStreamNonBlocking) != cudaSuccess) {
            s_side = 0;
        } else if (cudaEventCreateWithFlags(&ev_fork, cudaEventDisableTiming) != cudaSuccess ||
                   cudaEventCreateWithFlags(&ev_w, cudaEventDisableTiming) != cudaSuccess) {
            s_side = 0;
        }
    }

    if (s_side) {
        // side stream: wdiff alone (BW-bound) overlapped ONLY with
        // compute-bound group+hidden on the main stream.
        cudaEventRecord(ev_fork, 0);
        cudaStreamWaitEvent(s_side, ev_fork, 0);
        k_wdiff<<<dim3(1024, 2), 256, 0, s_side>>>(bw[3], sw[3]);
        cudaEventRecord(ev_w, s_side);
        k_group<<<1, B>>>(x);
        k_hidden<<<dim3(256, 4), 256>>>(x,
            bw[0], bb[0], bw[1], bb[1], bw[2], bb[2],
            sw[0], sb[0], sw[1], sb[1], sw[2], sb[2]);
        cudaStreamWaitEvent(0, ev_w, 0);
        k_gemm<<<dim3(8, 255), 256>>>(gumbel, bw[3], bb[3], sw[3], sb[3]);
    } else {
        k_group<<<1, B>>>(x);
        k_wdiff<<<dim3(1024, 2), 256>>>(bw[3], sw[3]);
        k_hidden<<<dim3(256, 4), 256>>>(x,
            bw[0], bb[0], bw[1], bb[1], bw[2], bb[2],
            sw[0], sb[0], sw[1], sb[1], sw[2], sb[2]);
        k_gemm<<<dim3(8, 255), 256>>>(gumbel, bw[3], bb[3], sw[3], sb[3]);
    }
    k_fix<<<296, 256>>>(gumbel, bw[3], bb[3], sw[3], sb[3]);
    k_expand<<<dim3(B, 10), 256>>>(out);
}